// round 13
// baseline (speedup 1.0000x reference)
#include <cuda_runtime.h>
#include <cuda_fp16.h>
#include <cstdint>

#define KT       2048
#define NH       96
#define M_TILE   128
#define KB       128
#define NITER    (KT / KB)     // 16
#define NTHREADS 256
#define NSTAGE   3

// Preconverted W (fp16) — scratch via __device__ global, no allocation
__device__ __half g_Whi[NH * KT];

// ---------------- SMEM layout (bytes) ----------------
// Each stage: A = 2 column-blocks x (128 rows x 128B) = 32768
//             B = 2 column-blocks x ( 96 rows x 128B) = 24576
#define SM_A       0u            // 3 x 32768
#define SM_B       98304u        // 3 x 24576
#define SM_TOTAL   172032u
#define A_STAGE    32768u
#define B_STAGE    24576u
#define A_KBLK     16384u
#define B_KBLK     12288u

// ---------------- helpers ----------------
__device__ __forceinline__ uint32_t smem_u32(const void* p) {
    uint32_t a;
    asm("{ .reg .u64 t; cvta.to.shared.u64 t, %1; cvt.u32.u64 %0, t; }" : "=r"(a) : "l"(p));
    return a;
}
__device__ __forceinline__ uint32_t sw128(uint32_t o) { return o ^ ((o >> 3) & 0x70u); }

__device__ __forceinline__ void sts128(uint32_t a, uint32_t v0, uint32_t v1,
                                       uint32_t v2, uint32_t v3) {
    asm volatile("st.shared.v4.b32 [%0], {%1,%2,%3,%4};"
                 :: "r"(a), "r"(v0), "r"(v1), "r"(v2), "r"(v3) : "memory");
}
__device__ __forceinline__ void cp16(uint32_t dst, const void* src) {
    asm volatile("cp.async.cg.shared.global [%0], [%1], 16;"
                 :: "r"(dst), "l"(src) : "memory");
}
__device__ __forceinline__ void cp_commit() {
    asm volatile("cp.async.commit_group;" ::: "memory");
}
__device__ __forceinline__ void cp_wait0() {
    asm volatile("cp.async.wait_group 0;" ::: "memory");
}
__device__ __forceinline__ void cp_wait1() {
    asm volatile("cp.async.wait_group 1;" ::: "memory");
}
__device__ __forceinline__ void ldsm_x4(uint32_t* r, uint32_t addr) {
    asm volatile("ldmatrix.sync.aligned.m8n8.x4.shared.b16 {%0,%1,%2,%3}, [%4];"
                 : "=r"(r[0]), "=r"(r[1]), "=r"(r[2]), "=r"(r[3]) : "r"(addr));
}
__device__ __forceinline__ void mma16816(float* c, const uint32_t* a,
                                         uint32_t b0, uint32_t b1) {
    asm volatile(
        "mma.sync.aligned.m16n8k16.row.col.f32.f16.f16.f32 "
        "{%0,%1,%2,%3}, {%4,%5,%6,%7}, {%8,%9}, {%0,%1,%2,%3};"
        : "+f"(c[0]), "+f"(c[1]), "+f"(c[2]), "+f"(c[3])
        : "r"(a[0]), "r"(a[1]), "r"(a[2]), "r"(a[3]), "r"(b0), "r"(b1));
}

// ---------------- W pre-convert kernel ----------------
__global__ void __launch_bounds__(256) convW_kernel(const float* __restrict__ W) {
    int i = blockIdx.x * 256 + threadIdx.x;
    g_Whi[i] = __float2half(W[i]);
}

// ---------------- main GEMM kernel ----------------
__global__ void __launch_bounds__(NTHREADS, 1)
mh96_kernel(const float* __restrict__ x, const float* __restrict__ bias,
            float* __restrict__ out)
{
    extern __shared__ __align__(1024) char smem[];
    const uint32_t sb = smem_u32(smem);
    const int tid = threadIdx.x;
    const int wid = tid >> 5;
    const int lid = tid & 31;
    const int m0  = blockIdx.x * M_TILE;

    const int wm = wid & 1;      // m-half: rows wm*64
    const int wn = wid >> 1;     // n-quarter: cols wn*24

    // raw f32 staging for x: 128 rows x 128 cols / 256 thr = 16 float4 (64 regs)
    float4 xr[8][2];

    auto loadXf = [&](int kc) {      // issue LDGs only
#pragma unroll
        for (int j = 0; j < 8; ++j) {
            int s = j * NTHREADS + tid;          // 2048 slots = 128 rows x 16 (32B units)
            int row = s >> 4, c32 = s & 15;
            const float4* p = reinterpret_cast<const float4*>(
                x + (size_t)(m0 + row) * KT + kc * KB + c32 * 8);
            xr[j][0] = p[0];
            xr[j][1] = p[1];
        }
    };
    auto cpW = [&](int kc, int buf) {
#pragma unroll
        for (int j = 0; j < 6; ++j) {
            int s = j * NTHREADS + tid;          // 1536 slots = 96 rows x 16 (16B units)
            int row = s >> 4, c16 = s & 15;
            int kb = c16 >> 3, c8 = c16 & 7;
            uint32_t off = (uint32_t)kb * B_KBLK + sw128((uint32_t)(row * 128 + c8 * 16));
            size_t go = (size_t)row * KT + kc * KB + c16 * 8;
            cp16(sb + SM_B + (uint32_t)buf * B_STAGE + off, g_Whi + go);
        }
    };
    auto cvtStsX = [&](int buf) {    // convert staged f32 -> half2, store to ring buf
#pragma unroll
        for (int j = 0; j < 8; ++j) {
            int s = j * NTHREADS + tid;
            int row = s >> 4, c32 = s & 15;
            int kb = c32 >> 3, c8 = c32 & 7;     // 32B f32 -> 16B half at col c8*16 in block kb
            uint32_t off = (uint32_t)kb * A_KBLK + sw128((uint32_t)(row * 128 + c8 * 16));
            __half2 h0 = __float22half2_rn(make_float2(xr[j][0].x, xr[j][0].y));
            __half2 h1 = __float22half2_rn(make_float2(xr[j][0].z, xr[j][0].w));
            __half2 h2 = __float22half2_rn(make_float2(xr[j][1].x, xr[j][1].y));
            __half2 h3 = __float22half2_rn(make_float2(xr[j][1].z, xr[j][1].w));
            sts128(sb + SM_A + (uint32_t)buf * A_STAGE + off,
                   *reinterpret_cast<uint32_t*>(&h0), *reinterpret_cast<uint32_t*>(&h1),
                   *reinterpret_cast<uint32_t*>(&h2), *reinterpret_cast<uint32_t*>(&h3));
        }
    };

    float acc[4][3][4];
#pragma unroll
    for (int mt = 0; mt < 4; ++mt)
#pragma unroll
        for (int nt = 0; nt < 3; ++nt)
#pragma unroll
            for (int i = 0; i < 4; ++i) acc[mt][nt][i] = 0.f;

    // ldmatrix per-thread address components
    const int a_row8 = wm * 64 + (lid & 7) + ((lid >> 3) & 1) * 8;   // + mt*16
    const int a_koff = ((lid >> 4) & 1) * 16;                        // + ksl*32 + kb*A_KBLK
    const int b_row  = wn * 24 + (lid & 7);                          // + nt*8
    const int b_koff = (lid >> 3) * 16;                              // + kpl*64 + kb*B_KBLK

    // ---------------- prologue: fill stage 0, prefetch stage 1 ----------------
    loadXf(0);
    cpW(0, 0);  cp_commit();
    cvtStsX(0);                      // stalls on LDG(0) — prologue only
    loadXf(1);                       // xr <- chunk 1 (in flight)
    cpW(1, 1);  cp_commit();
    cp_wait1();                      // cpW(0) complete
    __syncthreads();                 // stage 0 ready

    for (int it = 0; it < NITER; ++it) {
        const int buf = it % NSTAGE;

        // stage it+1: convert + store x (LDG completed during previous iter's MMA)
        if (it + 1 < NITER) cvtStsX((it + 1) % NSTAGE);
        // stage it+2: issue global loads (a full iteration of slack)
        if (it + 2 < NITER) {
            loadXf(it + 2);
            cpW(it + 2, (it + 2) % NSTAGE);
            cp_commit();
        }

        const uint32_t ah_b = sb + SM_A + (uint32_t)buf * A_STAGE;
        const uint32_t bh_b = sb + SM_B + (uint32_t)buf * B_STAGE;

#pragma unroll
        for (int kp = 0; kp < 4; ++kp) {                 // 4 K32-pairs
            const int kbB = kp >> 1, kpl = kp & 1;
            uint32_t bh[3][4];
#pragma unroll
            for (int nt = 0; nt < 3; ++nt) {
                uint32_t boff = (uint32_t)kbB * B_KBLK +
                    sw128((uint32_t)((b_row + nt * 8) * 128 + kpl * 64 + b_koff));
                ldsm_x4(bh[nt], bh_b + boff);
            }
#pragma unroll
            for (int ks2 = 0; ks2 < 2; ++ks2) {
                const int ks = kp * 2 + ks2;             // 0..7
                const int kbA = ks >> 2, ksl = ks & 3;
                uint32_t a[4][4];
#pragma unroll
                for (int mt = 0; mt < 4; ++mt) {
                    uint32_t aoff = (uint32_t)kbA * A_KBLK +
                        sw128((uint32_t)((a_row8 + mt * 16) * 128 + ksl * 32 + a_koff));
                    ldsm_x4(a[mt], ah_b + aoff);
                }
#pragma unroll
                for (int mt = 0; mt < 4; ++mt)
#pragma unroll
                    for (int nt = 0; nt < 3; ++nt)
                        mma16816(acc[mt][nt], a[mt], bh[nt][2 * ks2], bh[nt][2 * ks2 + 1]);
            }
        }

        // wait for stage it+1's W (committed a full iteration ago)
        if (it + 2 < NITER) cp_wait1();
        else                cp_wait0();
        __syncthreads();
    }

    // ---------------- epilogue ----------------
    const int r0 = m0 + wm * 64 + (lid >> 2);
    const int c0 = wn * 24 + (lid & 3) * 2;
#pragma unroll
    for (int nt = 0; nt < 3; ++nt) {
        const int col = c0 + nt * 8;
        const float b0 = bias[col], b1 = bias[col + 1];
#pragma unroll
        for (int mt = 0; mt < 4; ++mt) {
            const int row = r0 + mt * 16;
            float2 v0 = make_float2(acc[mt][nt][0] + b0, acc[mt][nt][1] + b1);
            float2 v1 = make_float2(acc[mt][nt][2] + b0, acc[mt][nt][3] + b1);
            *reinterpret_cast<float2*>(out + (size_t)row * NH + col) = v0;
            *reinterpret_cast<float2*>(out + (size_t)(row + 8) * NH + col) = v1;
        }
    }
}

extern "C" void kernel_launch(void* const* d_in, const int* in_sizes, int n_in,
                              void* d_out, int out_size) {
    const float* x    = (const float*)d_in[0];  // [16384, 2048]
    const float* W    = (const float*)d_in[1];  // [96, 2048]
    const float* bias = (const float*)d_in[2];  // [96]
    float* out        = (float*)d_out;          // [16384, 96]

    cudaFuncSetAttribute(mh96_kernel, cudaFuncAttributeMaxDynamicSharedMemorySize, SM_TOTAL);
    convW_kernel<<<(NH * KT) / 256, 256>>>(W);
    mh96_kernel<<<16384 / M_TILE, NTHREADS, SM_TOTAL>>>(x, bias, out);
}

// round 14
// speedup vs baseline: 1.0928x; 1.0928x over previous
#include <cuda_runtime.h>
#include <cuda_fp16.h>
#include <cstdint>

#define KT       2048
#define NH       96
#define M_TILE   64
#define KB       64
#define NITER    (KT / KB)     // 32
#define NTHREADS 256
#define NSTAGE   3

// Preconverted W (fp16) — scratch via __device__ global, no allocation
__device__ __half g_Whi[NH * KT];

// ---------------- SMEM layout per CTA (bytes) ----------------
#define SM_A     0u              // 3 x 8192   (64 rows x 128B, x fp16)
#define SM_B     24576u          // 3 x 12288  (96 rows x 128B, W fp16)
#define SM_TOTAL 61440u
#define A_STAGE  8192u
#define B_STAGE  12288u

// ---------------- helpers ----------------
__device__ __forceinline__ uint32_t smem_u32(const void* p) {
    uint32_t a;
    asm("{ .reg .u64 t; cvta.to.shared.u64 t, %1; cvt.u32.u64 %0, t; }" : "=r"(a) : "l"(p));
    return a;
}
__device__ __forceinline__ uint32_t sw128(uint32_t o) { return o ^ ((o >> 3) & 0x70u); }

__device__ __forceinline__ void sts128(uint32_t a, uint32_t v0, uint32_t v1,
                                       uint32_t v2, uint32_t v3) {
    asm volatile("st.shared.v4.b32 [%0], {%1,%2,%3,%4};"
                 :: "r"(a), "r"(v0), "r"(v1), "r"(v2), "r"(v3) : "memory");
}
__device__ __forceinline__ void cp16(uint32_t dst, const void* src) {
    asm volatile("cp.async.cg.shared.global [%0], [%1], 16;"
                 :: "r"(dst), "l"(src) : "memory");
}
__device__ __forceinline__ void cp_commit() {
    asm volatile("cp.async.commit_group;" ::: "memory");
}
__device__ __forceinline__ void cp_wait0() {
    asm volatile("cp.async.wait_group 0;" ::: "memory");
}
__device__ __forceinline__ void cp_wait1() {
    asm volatile("cp.async.wait_group 1;" ::: "memory");
}
__device__ __forceinline__ void ldsm_x4(uint32_t* r, uint32_t addr) {
    asm volatile("ldmatrix.sync.aligned.m8n8.x4.shared.b16 {%0,%1,%2,%3}, [%4];"
                 : "=r"(r[0]), "=r"(r[1]), "=r"(r[2]), "=r"(r[3]) : "r"(addr));
}
__device__ __forceinline__ void mma16816(float* c, const uint32_t* a,
                                         uint32_t b0, uint32_t b1) {
    asm volatile(
        "mma.sync.aligned.m16n8k16.row.col.f32.f16.f16.f32 "
        "{%0,%1,%2,%3}, {%4,%5,%6,%7}, {%8,%9}, {%0,%1,%2,%3};"
        : "+f"(c[0]), "+f"(c[1]), "+f"(c[2]), "+f"(c[3])
        : "r"(a[0]), "r"(a[1]), "r"(a[2]), "r"(a[3]), "r"(b0), "r"(b1));
}

// ---------------- W pre-convert kernel ----------------
__global__ void __launch_bounds__(256) convW_kernel(const float* __restrict__ W) {
    int i = blockIdx.x * 256 + threadIdx.x;
    g_Whi[i] = __float2half(W[i]);
}

// ---------------- main GEMM kernel ----------------
__global__ void __launch_bounds__(NTHREADS, 2)
mh96_kernel(const float* __restrict__ x, const float* __restrict__ bias,
            float* __restrict__ out)
{
    extern __shared__ __align__(1024) char smem[];
    const uint32_t sb = smem_u32(smem);
    const int tid = threadIdx.x;
    const int wid = tid >> 5;
    const int lid = tid & 31;
    const int m0  = blockIdx.x * M_TILE;

    const int wm = wid & 1;      // m-half: rows wm*32 (2 mt of 16)
    const int wn = wid >> 1;     // n-quarter: cols wn*24

    // raw f32 staging for x: 64 rows x 64 cols / 256 thr = 4 float4 (16 regs)
    float4 xr[2][2];

    auto loadXf = [&](int kc) {      // issue LDGs only
#pragma unroll
        for (int j = 0; j < 2; ++j) {
            int s = j * NTHREADS + tid;          // 512 slots = 64 rows x 8 (16B units)
            int row = s >> 3, c8 = s & 7;
            const float4* p = reinterpret_cast<const float4*>(
                x + (size_t)(m0 + row) * KT + kc * KB + c8 * 8);
            xr[j][0] = p[0];
            xr[j][1] = p[1];
        }
    };
    auto cpW = [&](int kc, int buf) {
#pragma unroll
        for (int j = 0; j < 3; ++j) {
            int s = j * NTHREADS + tid;          // 768 slots = 96 rows x 8
            int row = s >> 3, c8 = s & 7;
            uint32_t off = sw128((uint32_t)(row * 128 + c8 * 16));
            size_t go = (size_t)row * KT + kc * KB + c8 * 8;
            cp16(sb + SM_B + (uint32_t)buf * B_STAGE + off, g_Whi + go);
        }
    };
    auto cvtStsX = [&](int buf) {    // convert staged f32 -> half2, store to ring buf
#pragma unroll
        for (int j = 0; j < 2; ++j) {
            int s = j * NTHREADS + tid;
            int row = s >> 3, c8 = s & 7;
            uint32_t off = sw128((uint32_t)(row * 128 + c8 * 16));
            __half2 h0 = __float22half2_rn(make_float2(xr[j][0].x, xr[j][0].y));
            __half2 h1 = __float22half2_rn(make_float2(xr[j][0].z, xr[j][0].w));
            __half2 h2 = __float22half2_rn(make_float2(xr[j][1].x, xr[j][1].y));
            __half2 h3 = __float22half2_rn(make_float2(xr[j][1].z, xr[j][1].w));
            sts128(sb + SM_A + (uint32_t)buf * A_STAGE + off,
                   *reinterpret_cast<uint32_t*>(&h0), *reinterpret_cast<uint32_t*>(&h1),
                   *reinterpret_cast<uint32_t*>(&h2), *reinterpret_cast<uint32_t*>(&h3));
        }
    };

    float acc[2][3][4];
#pragma unroll
    for (int mt = 0; mt < 2; ++mt)
#pragma unroll
        for (int nt = 0; nt < 3; ++nt)
#pragma unroll
            for (int i = 0; i < 4; ++i) acc[mt][nt][i] = 0.f;

    // ldmatrix per-thread address components
    const int a_row8 = wm * 32 + (lid & 7) + ((lid >> 3) & 1) * 8;   // + mt*16
    const int a_koff = ((lid >> 4) & 1) * 16;                        // + ks*32
    const int b_row  = wn * 24 + (lid & 7);                          // + nt*8
    const int b_koff = (lid >> 3) * 16;                              // + kp*64

    // ---------------- prologue: fill stage 0, prefetch stage 1 ----------------
    loadXf(0);
    cpW(0, 0);  cp_commit();
    cvtStsX(0);                      // stalls on LDG(0) — prologue only
    loadXf(1);                       // xr <- chunk 1 (in flight)
    cpW(1, 1);  cp_commit();
    cp_wait1();                      // cpW(0) complete
    __syncthreads();                 // stage 0 ready

    for (int it = 0; it < NITER; ++it) {
        const int buf = it % NSTAGE;

        // stage it+1: convert + store x (LDG completed during previous iter's MMA)
        if (it + 1 < NITER) cvtStsX((it + 1) % NSTAGE);
        // stage it+2: issue global loads (a full iteration of slack)
        if (it + 2 < NITER) {
            loadXf(it + 2);
            cpW(it + 2, (it + 2) % NSTAGE);
            cp_commit();
        }

        const uint32_t ah_b = sb + SM_A + (uint32_t)buf * A_STAGE;
        const uint32_t bh_b = sb + SM_B + (uint32_t)buf * B_STAGE;

#pragma unroll
        for (int kp = 0; kp < 2; ++kp) {
            uint32_t bh[3][4];
#pragma unroll
            for (int nt = 0; nt < 3; ++nt) {
                uint32_t boff = sw128((uint32_t)((b_row + nt * 8) * 128 + kp * 64 + b_koff));
                ldsm_x4(bh[nt], bh_b + boff);
            }
#pragma unroll
            for (int ks2 = 0; ks2 < 2; ++ks2) {
                const int ks = kp * 2 + ks2;
                uint32_t a[2][4];
#pragma unroll
                for (int mt = 0; mt < 2; ++mt) {
                    uint32_t aoff = sw128((uint32_t)((a_row8 + mt * 16) * 128 + ks * 32 + a_koff));
                    ldsm_x4(a[mt], ah_b + aoff);
                }
#pragma unroll
                for (int mt = 0; mt < 2; ++mt)
#pragma unroll
                    for (int nt = 0; nt < 3; ++nt)
                        mma16816(acc[mt][nt], a[mt], bh[nt][2 * ks2], bh[nt][2 * ks2 + 1]);
            }
        }

        // wait for stage it+1's W (committed a full iteration ago)
        if (it + 2 < NITER) cp_wait1();
        else                cp_wait0();
        __syncthreads();
    }

    // ---------------- epilogue ----------------
    const int r0 = m0 + wm * 32 + (lid >> 2);
    const int c0 = wn * 24 + (lid & 3) * 2;
#pragma unroll
    for (int nt = 0; nt < 3; ++nt) {
        const int col = c0 + nt * 8;
        const float b0 = bias[col], b1 = bias[col + 1];
#pragma unroll
        for (int mt = 0; mt < 2; ++mt) {
            const int row = r0 + mt * 16;
            float2 v0 = make_float2(acc[mt][nt][0] + b0, acc[mt][nt][1] + b1);
            float2 v1 = make_float2(acc[mt][nt][2] + b0, acc[mt][nt][3] + b1);
            *reinterpret_cast<float2*>(out + (size_t)row * NH + col) = v0;
            *reinterpret_cast<float2*>(out + (size_t)(row + 8) * NH + col) = v1;
        }
    }
}

extern "C" void kernel_launch(void* const* d_in, const int* in_sizes, int n_in,
                              void* d_out, int out_size) {
    const float* x    = (const float*)d_in[0];  // [16384, 2048]
    const float* W    = (const float*)d_in[1];  // [96, 2048]
    const float* bias = (const float*)d_in[2];  // [96]
    float* out        = (float*)d_out;          // [16384, 96]

    cudaFuncSetAttribute(mh96_kernel, cudaFuncAttributeMaxDynamicSharedMemorySize, SM_TOTAL);
    convW_kernel<<<(NH * KT) / 256, 256>>>(W);
    mh96_kernel<<<16384 / M_TILE, NTHREADS, SM_TOTAL>>>(x, bias, out);
}